// round 9
// baseline (speedup 1.0000x reference)
#include <cuda_runtime.h>
#include <math.h>

// 256 threads/CTA, 4 rows per CTA, cp.async-staged (register-free MLP),
// SINGLE barrier per row via double-buffered compaction/wtot pipeline:
// during row r's scatter, row r+1 is read from smem staging, its ballots
// computed and warp totals published into the alternate buffer; one
// __syncthreads() then means both "scatter r complete" and "wtot r+1
// visible". Epilogue of row r overlaps scatter of row r+1 (disjoint
// buffers). Streaming __stcs stores; w/b loaded once per CTA.

#define SIZE 1024
#define THREADS 256
#define ROWS 4

__global__ __launch_bounds__(THREADS, 6)
void nan_dense_kernel(const float* __restrict__ X,
                      const float4* __restrict__ w4,
                      const float4* __restrict__ b4,
                      float4* __restrict__ out4)
{
    __shared__ float raw[ROWS * SIZE];      // 16 KB staging
    __shared__ float cmp[2][SIZE];          // 8 KB double-buffered compaction
    __shared__ int wtot[2][8];

    const int t    = threadIdx.x;
    const int lane = t & 31;
    const int wid  = t >> 5;
    const int V    = SIZE / 4;

    const long long r0 = (long long)blockIdx.x * ROWS;
    const float* gsrc = X + r0 * SIZE + (t << 2);
    const unsigned raw_sa = (unsigned)__cvta_generic_to_shared(raw) + (t << 4);

    // Stage all four rows; one commit group per row (FIFO retirement).
#pragma unroll
    for (int r = 0; r < ROWS; ++r) {
        asm volatile(
            "cp.async.cg.shared.global [%0], [%1], 16;\n\t"
            "cp.async.commit_group;\n"
            :: "r"(raw_sa + r * (SIZE * 4)), "l"(gsrc + r * SIZE)
            : "memory");
    }

    const float4 wv = __ldg(&w4[t]);
    const float4 bv = __ldg(&b4[t]);
    const unsigned lt = (1u << lane) - 1u;
    const int base = t << 2;

    // Prologue: row 0 ballots -> wtot[0].
    float vc[4];
    int pre;
    {
        asm volatile("cp.async.wait_group 3;" ::: "memory");
        const float4 cur = reinterpret_cast<const float4*>(raw)[t];
        vc[0] = cur.x; vc[1] = cur.y; vc[2] = cur.z; vc[3] = cur.w;
        int wt = 0; pre = 0;
#pragma unroll
        for (int k = 0; k < 4; ++k) {
            const unsigned m = __ballot_sync(0xffffffffu, isfinite(vc[k]));
            pre += __popc(m & lt);
            wt  += __popc(m);
        }
        if (lane == 0) wtot[0][wid] = wt;
    }
    __syncthreads();                       // wtot[0] visible

#pragma unroll
    for (int r = 0; r < ROWS; ++r) {
        const int buf = r & 1;

        // Cross-warp offsets + block total for row r (broadcast LDS).
        int off = 0, total = 0;
#pragma unroll
        for (int i = 0; i < 8; ++i) {
            const int ti = wtot[buf][i];
            total += ti;
            if (i < wid) off += ti;
        }

        // Stable scatter of row r into its buffer.
        int pos = off + pre;
#pragma unroll
        for (int k = 0; k < 4; ++k) {
            if (isfinite(vc[k])) cmp[buf][pos++] = vc[k];
        }

        // Pipeline: fetch row r+1 from staging, ballots, publish wtot.
        float vn[4] = {0.0f, 0.0f, 0.0f, 0.0f};
        int npre = 0;
        if (r + 1 < ROWS) {
            if (r == 0)      asm volatile("cp.async.wait_group 2;" ::: "memory");
            else if (r == 1) asm volatile("cp.async.wait_group 1;" ::: "memory");
            else             asm volatile("cp.async.wait_group 0;" ::: "memory");

            const float4 nx = reinterpret_cast<const float4*>(raw)[(r + 1) * V + t];
            vn[0] = nx.x; vn[1] = nx.y; vn[2] = nx.z; vn[3] = nx.w;
            int wt = 0;
#pragma unroll
            for (int k = 0; k < 4; ++k) {
                const unsigned m = __ballot_sync(0xffffffffu, isfinite(vn[k]));
                npre += __popc(m & lt);
                wt   += __popc(m);
            }
            if (lane == 0) wtot[buf ^ 1][wid] = wt;
        }

        __syncthreads();   // scatter r complete AND wtot[r+1] visible

        // Epilogue row r (overlaps next iteration's scatter into other buf).
        const float4 sv = reinterpret_cast<const float4*>(cmp[buf])[t];
        float4 o;
        o.x = (base + 0 < total) ? fmaf(sv.x, wv.x, bv.x) : 0.0f;
        o.y = (base + 1 < total) ? fmaf(sv.y, wv.y, bv.y) : 0.0f;
        o.z = (base + 2 < total) ? fmaf(sv.z, wv.z, bv.z) : 0.0f;
        o.w = (base + 3 < total) ? fmaf(sv.w, wv.w, bv.w) : 0.0f;
        __stcs(&out4[(r0 + r) * V + t], o);

        vc[0] = vn[0]; vc[1] = vn[1]; vc[2] = vn[2]; vc[3] = vn[3];
        pre = npre;
    }
}

extern "C" void kernel_launch(void* const* d_in, const int* in_sizes, int n_in,
                              void* d_out, int out_size)
{
    const float* X = (const float*)d_in[0];
    const float* w = (const float*)d_in[1];
    const float* b = (const float*)d_in[2];
    float* out = (float*)d_out;

    const int batch = in_sizes[0] / SIZE;   // 131072 (multiple of 4)
    nan_dense_kernel<<<batch / ROWS, THREADS>>>(
        X,
        reinterpret_cast<const float4*>(w),
        reinterpret_cast<const float4*>(b),
        reinterpret_cast<float4*>(out));
}